// round 2
// baseline (speedup 1.0000x reference)
#include <cuda_runtime.h>
#include <cuda_bf16.h>
#include <math.h>

// ---------------- problem constants (fixed by the reference module) ----------
#define NB    4        // batch
#define LQ    5440     // queries
#define CCH   256      // channels
#define NH    8        // heads
#define NL    4        // levels
#define NP    4        // points
#define DH    32       // head dim
#define LEN_IN 5440
#define MROWS (NB * LQ)   // 21760 = 170 * 128

__device__ __constant__ int c_W[NL]  = {64, 32, 16, 8};
__device__ __constant__ int c_Hh[NL] = {64, 32, 16, 8};
__device__ __constant__ int c_S0[NL] = {0, 4096, 5120, 5376};

// ---------------- scratch (no allocations allowed) ---------------------------
__device__ float g_value[(size_t)MROWS * CCH];   // projected value  (n,tok,h,d)
__device__ float g_off  [(size_t)MROWS * CCH];   // offsets          (n,q,h,l,p,2)
__device__ float g_attn [(size_t)MROWS * 128];   // attn logits      (n,q,h,lp)
__device__ float g_samp [(size_t)MROWS * CCH];   // attended value   (n,q,h,d)

// ---------------- fp32 SGEMM: C = A(MxK) * B(KxN) + bias ---------------------
#define BM 128
#define BN 128
#define BK 8
#define TM 8
#define TN 8

__global__ __launch_bounds__(256)
void sgemm_bias(int M, int Nn, int K,
                const float* __restrict__ A,
                const float* __restrict__ B,
                const float* __restrict__ bias,
                float* __restrict__ C)
{
    __shared__ float As[BK * BM];   // transposed A tile
    __shared__ float Bs[BK * BN];

    const int crow = blockIdx.y;
    const int ccol = blockIdx.x;

    A += (size_t)crow * BM * K;
    B += (size_t)ccol * BN;
    C += (size_t)crow * BM * Nn + (size_t)ccol * BN;
    bias += (size_t)ccol * BN;

    const int tid = threadIdx.x;
    const int threadRow = tid / (BN / TN);   // 0..15
    const int threadCol = tid % (BN / TN);   // 0..15
    const int innerRowA = tid / (BK / 4);    // 0..127
    const int innerColA = tid % (BK / 4);    // 0..1
    const int innerRowB = tid / (BN / 4);    // 0..7
    const int innerColB = tid % (BN / 4);    // 0..31

    float acc[TM * TN] = {0.0f};
    float regM[TM];
    float regN[TN];

    for (int k0 = 0; k0 < K; k0 += BK) {
        float4 a4 = *reinterpret_cast<const float4*>(
            &A[(size_t)innerRowA * K + innerColA * 4]);
        As[(innerColA * 4 + 0) * BM + innerRowA] = a4.x;
        As[(innerColA * 4 + 1) * BM + innerRowA] = a4.y;
        As[(innerColA * 4 + 2) * BM + innerRowA] = a4.z;
        As[(innerColA * 4 + 3) * BM + innerRowA] = a4.w;

        *reinterpret_cast<float4*>(&Bs[innerRowB * BN + innerColB * 4]) =
            *reinterpret_cast<const float4*>(
                &B[(size_t)innerRowB * Nn + innerColB * 4]);

        __syncthreads();
        A += BK;
        B += (size_t)BK * Nn;

        #pragma unroll
        for (int k = 0; k < BK; k++) {
            #pragma unroll
            for (int i = 0; i < TM; i++)
                regM[i] = As[k * BM + threadRow * TM + i];
            #pragma unroll
            for (int j = 0; j < TN; j++)
                regN[j] = Bs[k * BN + threadCol * TN + j];
            #pragma unroll
            for (int i = 0; i < TM; i++)
                #pragma unroll
                for (int j = 0; j < TN; j++)
                    acc[i * TN + j] += regM[i] * regN[j];
        }
        __syncthreads();
    }

    // hoist bias into registers once (per-thread columns are fixed)
    float bj[TN];
    #pragma unroll
    for (int j = 0; j < TN; j++)
        bj[j] = bias[threadCol * TN + j];

    #pragma unroll
    for (int i = 0; i < TM; i++) {
        const int row = threadRow * TM + i;
        #pragma unroll
        for (int j = 0; j < TN; j += 4) {
            const int col = threadCol * TN + j;
            float4 o;
            o.x = acc[i * TN + j + 0] + bj[j + 0];
            o.y = acc[i * TN + j + 1] + bj[j + 1];
            o.z = acc[i * TN + j + 2] + bj[j + 2];
            o.w = acc[i * TN + j + 3] + bj[j + 3];
            *reinterpret_cast<float4*>(&C[(size_t)row * Nn + col]) = o;
        }
    }
}

// ---------------- sampling + softmax + attention-weighted sum ----------------
// 1 block per (n,q). 8 warps = 8 heads. lane = channel d (0..31).
__global__ __launch_bounds__(256)
void sample_kernel(const float* __restrict__ refp,   // (N, LQ, NL, 2)
                   float* __restrict__ samp)          // (N, LQ, NH*DH)
{
    const int nq = blockIdx.x;          // 0 .. MROWS-1
    const int n  = nq / LQ;

    __shared__ float s_off[CCH];
    __shared__ float s_ref[NL * 2];

    const int tid = threadIdx.x;
    s_off[tid] = g_off[(size_t)nq * CCH + tid];
    if (tid < NL * 2) s_ref[tid] = refp[(size_t)nq * (NL * 2) + tid];
    __syncthreads();

    const int h = tid >> 5;
    const int d = tid & 31;

    // softmax over 16 logits (computed redundantly per lane, broadcast loads)
    const float* lg = &g_attn[(size_t)nq * 128 + h * 16];
    float w[16];
    float mx = -1e30f;
    #pragma unroll
    for (int i = 0; i < 16; i++) { w[i] = lg[i]; mx = fmaxf(mx, w[i]); }
    float ssum = 0.0f;
    #pragma unroll
    for (int i = 0; i < 16; i++) { w[i] = __expf(w[i] - mx); ssum += w[i]; }
    const float inv = 1.0f / ssum;

    const float* vbase = g_value + (size_t)n * LEN_IN * CCH;
    float acc = 0.0f;

    #pragma unroll
    for (int l = 0; l < NL; l++) {
        const int W  = c_W[l];
        const int HH = c_Hh[l];
        const int S0 = c_S0[l];
        const float rx = s_ref[l * 2 + 0];
        const float ry = s_ref[l * 2 + 1];
        #pragma unroll
        for (int p = 0; p < NP; p++) {
            const float ox = s_off[h * 32 + l * 8 + p * 2 + 0];
            const float oy = s_off[h * 32 + l * 8 + p * 2 + 1];
            const float locx = fminf(fmaxf(rx + ox, 0.0f), 1.0f);
            const float locy = fminf(fmaxf(ry + oy, 0.0f), 1.0f);
            const float x = locx * (float)W  - 0.5f;
            const float y = locy * (float)HH - 0.5f;
            const int xf = (int)floorf(x);
            const int yf = (int)floorf(y);
            const int x0i = min(max(xf,     0), W  - 1);
            const int x1i = min(max(xf + 1, 0), W  - 1);
            const int y0i = min(max(yf,     0), HH - 1);
            const int y1i = min(max(yf + 1, 0), HH - 1);
            // weights use the CLIPPED corner coordinates (matches reference)
            const float wx1 = (float)x1i - x;   // (x1f - x)
            const float wx0 = x - (float)x0i;   // (x - x0f)
            const float wy1 = (float)y1i - y;   // (y1f - y)
            const float wy0 = y - (float)y0i;   // (y - y0f)

            const size_t ta = (size_t)(S0 + y0i * W + x0i);
            const size_t tb = (size_t)(S0 + y1i * W + x0i);
            const size_t tc = (size_t)(S0 + y0i * W + x1i);
            const size_t td = (size_t)(S0 + y1i * W + x1i);
            const float va = vbase[(ta * NH + h) * DH + d];
            const float vb = vbase[(tb * NH + h) * DH + d];
            const float vc = vbase[(tc * NH + h) * DH + d];
            const float vd = vbase[(td * NH + h) * DH + d];

            const float bil = wx1 * wy1 * va + wx1 * wy0 * vb
                            + wx0 * wy1 * vc + wx0 * wy0 * vd;
            acc += (w[l * 4 + p] * inv) * bil;
        }
    }

    samp[(size_t)nq * CCH + tid] = acc;
}

// ---------------- launch ------------------------------------------------------
extern "C" void kernel_launch(void* const* d_in, const int* in_sizes, int n_in,
                              void* d_out, int out_size)
{
    const float* query  = (const float*)d_in[0];   // (N, LQ, C)
    const float* refp   = (const float*)d_in[1];   // (N, LQ, L, 2)
    const float* inputf = (const float*)d_in[2];   // (N, LEN_IN, C)
    // d_in[3], d_in[4]: spatial shapes / level starts (compile-time constants)
    const float* w_off  = (const float*)d_in[5];   // (C, 256)
    const float* b_off  = (const float*)d_in[6];
    const float* w_attn = (const float*)d_in[7];   // (C, 128)
    const float* b_attn = (const float*)d_in[8];
    const float* w_val  = (const float*)d_in[9];   // (C, C)
    const float* b_val  = (const float*)d_in[10];
    const float* w_out  = (const float*)d_in[11];  // (C, C)
    const float* b_out  = (const float*)d_in[12];
    float* out = (float*)d_out;

    float *gv, *go, *ga, *gs;
    cudaGetSymbolAddress((void**)&gv, g_value);
    cudaGetSymbolAddress((void**)&go, g_off);
    cudaGetSymbolAddress((void**)&ga, g_attn);
    cudaGetSymbolAddress((void**)&gs, g_samp);

    const dim3 blk(256);
    const dim3 grid256(CCH / BN, MROWS / BM);   // (2, 170)
    const dim3 grid128(128 / BN, MROWS / BM);   // (1, 170)

    // value = input_flatten @ w_val + b_val
    sgemm_bias<<<grid256, blk>>>(MROWS, CCH, CCH, inputf, w_val, b_val, gv);
    // off = query @ w_off + b_off
    sgemm_bias<<<grid256, blk>>>(MROWS, CCH, CCH, query, w_off, b_off, go);
    // attn logits = query @ w_attn + b_attn
    sgemm_bias<<<grid128, blk>>>(MROWS, 128, CCH, query, w_attn, b_attn, ga);
    // bilinear sampling + softmax + head-wise attention sum
    sample_kernel<<<MROWS, blk>>>(refp, gs);
    // out = samp @ w_out + b_out
    sgemm_bias<<<grid256, blk>>>(MROWS, CCH, CCH, gs, w_out, b_out, out);
}

// round 4
// speedup vs baseline: 1.3188x; 1.3188x over previous
#include <cuda_runtime.h>
#include <cuda_bf16.h>
#include <math.h>

// ---------------- problem constants (fixed by the reference module) ----------
#define NB    4        // batch
#define LQ    5440     // queries
#define CCH   256      // channels
#define NH    8        // heads
#define NL    4        // levels
#define NP    4        // points
#define DH    32       // head dim
#define LEN_IN 5440
#define MROWS (NB * LQ)   // 21760 = 170 * 128
#define QPB   4           // queries per block in sample kernel

// ---------------- scratch (no allocations allowed) ---------------------------
__device__ float g_value[(size_t)MROWS * CCH];   // projected value  (n,tok,h,d)
__device__ float g_off  [(size_t)MROWS * CCH];   // offsets          (n,q,h,l,p,2)
__device__ float g_attn [(size_t)MROWS * 128];   // attn logits      (n,q,h,lp)
__device__ float g_samp [(size_t)MROWS * CCH];   // attended value   (n,q,h,d)

// ---------------- fp32 SGEMM: C = A(MxK) * B(KxN) + bias ---------------------
#define BM 128
#define BN 128
#define BK 8
#define TM 8
#define TN 8

__global__ __launch_bounds__(256)
void sgemm_bias(int M, int Nn, int K,
                const float* __restrict__ A,
                const float* __restrict__ B,
                const float* __restrict__ bias,
                float* __restrict__ C)
{
    __shared__ float As[BK * BM];   // transposed A tile
    __shared__ float Bs[BK * BN];

    const int crow = blockIdx.y;
    const int ccol = blockIdx.x;

    A += (size_t)crow * BM * K;
    B += (size_t)ccol * BN;
    C += (size_t)crow * BM * Nn + (size_t)ccol * BN;
    bias += (size_t)ccol * BN;

    const int tid = threadIdx.x;
    const int threadRow = tid / (BN / TN);   // 0..15
    const int threadCol = tid % (BN / TN);   // 0..15
    const int innerRowA = tid / (BK / 4);    // 0..127
    const int innerColA = tid % (BK / 4);    // 0..1
    const int innerRowB = tid / (BN / 4);    // 0..7
    const int innerColB = tid % (BN / 4);    // 0..31

    float acc[TM * TN] = {0.0f};
    float regM[TM];
    float regN[TN];

    for (int k0 = 0; k0 < K; k0 += BK) {
        float4 a4 = *reinterpret_cast<const float4*>(
            &A[(size_t)innerRowA * K + innerColA * 4]);
        As[(innerColA * 4 + 0) * BM + innerRowA] = a4.x;
        As[(innerColA * 4 + 1) * BM + innerRowA] = a4.y;
        As[(innerColA * 4 + 2) * BM + innerRowA] = a4.z;
        As[(innerColA * 4 + 3) * BM + innerRowA] = a4.w;

        *reinterpret_cast<float4*>(&Bs[innerRowB * BN + innerColB * 4]) =
            *reinterpret_cast<const float4*>(
                &B[(size_t)innerRowB * Nn + innerColB * 4]);

        __syncthreads();
        A += BK;
        B += (size_t)BK * Nn;

        #pragma unroll
        for (int k = 0; k < BK; k++) {
            #pragma unroll
            for (int i = 0; i < TM; i++)
                regM[i] = As[k * BM + threadRow * TM + i];
            #pragma unroll
            for (int j = 0; j < TN; j++)
                regN[j] = Bs[k * BN + threadCol * TN + j];
            #pragma unroll
            for (int i = 0; i < TM; i++)
                #pragma unroll
                for (int j = 0; j < TN; j++)
                    acc[i * TN + j] += regM[i] * regN[j];
        }
        __syncthreads();
    }

    float bj[TN];
    #pragma unroll
    for (int j = 0; j < TN; j++)
        bj[j] = bias[threadCol * TN + j];

    #pragma unroll
    for (int i = 0; i < TM; i++) {
        const int row = threadRow * TM + i;
        #pragma unroll
        for (int j = 0; j < TN; j += 4) {
            const int col = threadCol * TN + j;
            float4 o;
            o.x = acc[i * TN + j + 0] + bj[j + 0];
            o.y = acc[i * TN + j + 1] + bj[j + 1];
            o.z = acc[i * TN + j + 2] + bj[j + 2];
            o.w = acc[i * TN + j + 3] + bj[j + 3];
            *reinterpret_cast<float4*>(&C[(size_t)row * Nn + col]) = o;
        }
    }
}

// ---------------- sampling: two-phase, 4 queries per block -------------------
// Phase 1: 1 thread per (q,h,point): softmax weight + bilinear weights (folded
//          with attn) + 4 clipped corner token indices -> smem.
// Phase 2: thread = (q,h,d-quad): pure float4 gather + FMA using smem scalars.
__global__ __launch_bounds__(256)
void sample_kernel(const float* __restrict__ refp,   // (N, LQ, NL, 2)
                   float* __restrict__ samp)          // (N, LQ, NH*DH)
{
    const int nq0 = blockIdx.x * QPB;
    const int tid = threadIdx.x;

    __shared__ float4 s_w[QPB * 128];
    __shared__ int4   s_t[QPB * 128];

    // ---------- phase 1 ----------
    #pragma unroll
    for (int rep = 0; rep < 2; rep++) {
        const int task = tid + rep * 256;        // 0..511
        const int q    = task >> 7;              // 0..3
        const int rest = task & 127;             // h*16 + i
        const int h    = rest >> 4;
        const int i    = rest & 15;              // l*4 + p
        const int l    = i >> 2;
        const int nq   = nq0 + q;

        // softmax over the 16 logits of (nq,h); 16-lane segments are aligned
        float logit = g_attn[(size_t)nq * 128 + rest];
        float mx = logit;
        #pragma unroll
        for (int m = 8; m; m >>= 1)
            mx = fmaxf(mx, __shfl_xor_sync(0xffffffffu, mx, m, 16));
        float e = __expf(logit - mx);
        float ssum = e;
        #pragma unroll
        for (int m = 8; m; m >>= 1)
            ssum += __shfl_xor_sync(0xffffffffu, ssum, m, 16);
        const float aw = e * (1.0f / ssum);

        // level geometry: W=H=64>>l ; S0 = (16384 - (16384>>2l)) / 3
        const int W  = 64 >> l;
        const int S0 = (16384 - (16384 >> (2 * l))) / 3;

        const float2 off = *reinterpret_cast<const float2*>(
            &g_off[(size_t)nq * CCH + rest * 2]);           // h*32 + i*2
        const float2 rp  = *reinterpret_cast<const float2*>(
            &refp[((size_t)nq * NL + l) * 2]);

        const float locx = fminf(fmaxf(rp.x + off.x, 0.0f), 1.0f);
        const float locy = fminf(fmaxf(rp.y + off.y, 0.0f), 1.0f);
        const float x = locx * (float)W - 0.5f;
        const float y = locy * (float)W - 0.5f;
        const int xf = (int)floorf(x);
        const int yf = (int)floorf(y);
        const int x0i = min(max(xf,     0), W - 1);
        const int x1i = min(max(xf + 1, 0), W - 1);
        const int y0i = min(max(yf,     0), W - 1);
        const int y1i = min(max(yf + 1, 0), W - 1);
        // weights from CLIPPED corner coordinates (matches reference exactly)
        const float wx1 = (float)x1i - x;
        const float wx0 = x - (float)x0i;
        const float wy1 = (float)y1i - y;
        const float wy0 = y - (float)y0i;

        s_w[task] = make_float4(wx1 * wy1 * aw, wx1 * wy0 * aw,
                                wx0 * wy1 * aw, wx0 * wy0 * aw);
        s_t[task] = make_int4(S0 + y0i * W + x0i,
                              S0 + y1i * W + x0i,
                              S0 + y0i * W + x1i,
                              S0 + y1i * W + x1i);
    }
    __syncthreads();

    // ---------- phase 2 ----------
    const int q  = tid >> 6;        // 0..3
    const int r  = tid & 63;
    const int h  = r >> 3;          // 0..7
    const int d4 = r & 7;           // float4 group within head dim
    const int nq = nq0 + q;
    const int n  = nq / LQ;

    // token t lives at g_value[n*LEN_IN*256 + t*256 + h*32 + d4*4]
    const float4* vbase = reinterpret_cast<const float4*>(
        g_value + (size_t)n * LEN_IN * CCH + h * DH + d4 * 4);

    float4 acc = make_float4(0.0f, 0.0f, 0.0f, 0.0f);
    const int tb0 = q * 128 + h * 16;

    #pragma unroll
    for (int i = 0; i < 16; i++) {
        const float4 w  = s_w[tb0 + i];
        const int4   tt = s_t[tb0 + i];
        const float4 va = vbase[(size_t)tt.x * (CCH / 4)];
        const float4 vb = vbase[(size_t)tt.y * (CCH / 4)];
        const float4 vc = vbase[(size_t)tt.z * (CCH / 4)];
        const float4 vd = vbase[(size_t)tt.w * (CCH / 4)];
        acc.x += w.x * va.x + w.y * vb.x + w.z * vc.x + w.w * vd.x;
        acc.y += w.x * va.y + w.y * vb.y + w.z * vc.y + w.w * vd.y;
        acc.z += w.x * va.z + w.y * vb.z + w.z * vc.z + w.w * vd.z;
        acc.w += w.x * va.w + w.y * vb.w + w.z * vc.w + w.w * vd.w;
    }

    *reinterpret_cast<float4*>(&samp[(size_t)nq * CCH + h * DH + d4 * 4]) = acc;
}

// ---------------- launch ------------------------------------------------------
extern "C" void kernel_launch(void* const* d_in, const int* in_sizes, int n_in,
                              void* d_out, int out_size)
{
    const float* query  = (const float*)d_in[0];   // (N, LQ, C)
    const float* refp   = (const float*)d_in[1];   // (N, LQ, L, 2)
    const float* inputf = (const float*)d_in[2];   // (N, LEN_IN, C)
    // d_in[3], d_in[4]: spatial shapes / level starts (compile-time constants)
    const float* w_off  = (const float*)d_in[5];   // (C, 256)
    const float* b_off  = (const float*)d_in[6];
    const float* w_attn = (const float*)d_in[7];   // (C, 128)
    const float* b_attn = (const float*)d_in[8];
    const float* w_val  = (const float*)d_in[9];   // (C, C)
    const float* b_val  = (const float*)d_in[10];
    const float* w_out  = (const float*)d_in[11];  // (C, C)
    const float* b_out  = (const float*)d_in[12];
    float* out = (float*)d_out;

    float *gv, *go, *ga, *gs;
    cudaGetSymbolAddress((void**)&gv, g_value);
    cudaGetSymbolAddress((void**)&go, g_off);
    cudaGetSymbolAddress((void**)&ga, g_attn);
    cudaGetSymbolAddress((void**)&gs, g_samp);

    const dim3 blk(256);
    const dim3 grid256(CCH / BN, MROWS / BM);   // (2, 170)
    const dim3 grid128(128 / BN, MROWS / BM);   // (1, 170)

    // value = input_flatten @ w_val + b_val
    sgemm_bias<<<grid256, blk>>>(MROWS, CCH, CCH, inputf, w_val, b_val, gv);
    // off = query @ w_off + b_off
    sgemm_bias<<<grid256, blk>>>(MROWS, CCH, CCH, query, w_off, b_off, go);
    // attn logits = query @ w_attn + b_attn
    sgemm_bias<<<grid128, blk>>>(MROWS, 128, CCH, query, w_attn, b_attn, ga);
    // bilinear sampling + softmax + head-wise attention sum
    sample_kernel<<<MROWS / QPB, blk>>>(refp, gs);
    // out = samp @ w_out + b_out
    sgemm_bias<<<grid256, blk>>>(MROWS, CCH, CCH, gs, w_out, b_out, out);
}